// round 17
// baseline (speedup 1.0000x reference)
#include <cuda_runtime.h>
#include <cuda_fp16.h>
#include <math.h>
#include <stdint.h>

// conv_nonlinear R12: M=32 per warp (two M=16 tiles share one B ldmatrix
// stream -> half the LDSM per output, two independent MMA chains per warp)
// + scalar-immediate GELU (A&S 7.1.26; no packed-constant registers).
// fp16: A single-plane, B hi/lo 2-pass, fp32 accum. 448 thr / 14 warps.

#define NB 16
#define NK 64
#define LSEQ 1000
#define NOUT 986
#define MTOT (NB*NOUT)     // 15776
#define NTILE (MTOT/16)    // 986
#define NPAIR (NTILE/2)    // 493
#define NTH 448
#define NWARP 14
#define NGRP 7
#define TPP 71             // pairs per group: 7*71 = 497 >= 493

#define WO0 0
#define WO1 5760
#define WO2 14208
#define WO3 24192
#define WO4 32512
#define WTOTAL 38144

#define SM_WHI  0
#define SM_WLO  (WTOTAL*2)          // 76288
#define SM_BIAS (WTOTAL*4)          // 152576
#define SM_HW   (SM_BIAS + 416*4)   // 154240
#define SMEM_TOTAL (SM_HW + 64*4)   // 154496

__device__ __half g_imh[MTOT * 64];

__device__ __forceinline__ uint32_t smem_u32(const void* p) {
    uint32_t a;
    asm("{ .reg .u64 t; cvta.to.shared.u64 t, %1; cvt.u32.u64 %0, t; }"
        : "=r"(a) : "l"(p));
    return a;
}
__device__ __forceinline__ float ex2f(float x) {
    float r; asm("ex2.approx.f32 %0, %1;" : "=f"(r) : "f"(x)); return r;
}
__device__ __forceinline__ float rcpf(float x) {
    float r; asm("rcp.approx.f32 %0, %1;" : "=f"(r) : "f"(x)); return r;
}
// exact-GELU, branch-free scalar (A&S 7.1.26 erf, abs err < 2e-6)
__device__ __forceinline__ float gelu1(float v) {
    float av = fabsf(v);
    float e  = ex2f(v * v * -0.7213475204444817f);          // exp(-v^2/2)
    float t  = rcpf(fmaf(av, 0.23164690834590862f, 1.0f));  // p/sqrt2
    float p  = fmaf(1.061405429f, t, -1.453152027f);
    p = fmaf(p, t, 1.421413741f);
    p = fmaf(p, t, -0.284496736f);
    p = fmaf(p, t, 0.254829592f);
    p = p * t;
    return fmaf(v + av, 0.5f, -0.5f * (av * p * e));
}
// pack (g0,g1) -> fp16x2, g0 low
__device__ __forceinline__ uint32_t pack_f16(float g0, float g1) {
    uint32_t r;
    asm("cvt.rn.f16x2.f32 %0, %1, %2;" : "=r"(r) : "f"(g1), "f"(g0));
    return r;
}
__device__ __forceinline__ void ldm_x4(uint32_t* r, uint32_t addr) {
    asm volatile("ldmatrix.sync.aligned.m8n8.x4.shared.b16 {%0,%1,%2,%3}, [%4];"
                 : "=r"(r[0]), "=r"(r[1]), "=r"(r[2]), "=r"(r[3]) : "r"(addr));
}
__device__ __forceinline__ void ldm_x2(uint32_t& b0, uint32_t& b1, uint32_t addr) {
    asm volatile("ldmatrix.sync.aligned.m8n8.x2.shared.b16 {%0,%1}, [%2];"
                 : "=r"(b0), "=r"(b1) : "r"(addr));
}
__device__ __forceinline__ void mma16816(float& c0, float& c1, float& c2, float& c3,
                                         const uint32_t* a, uint32_t b0, uint32_t b1) {
    asm volatile(
        "mma.sync.aligned.m16n8k16.row.col.f32.f16.f16.f32 "
        "{%0,%1,%2,%3},{%4,%5,%6,%7},{%8,%9},{%0,%1,%2,%3};"
        : "+f"(c0), "+f"(c1), "+f"(c2), "+f"(c3)
        : "r"(a[0]), "r"(a[1]), "r"(a[2]), "r"(a[3]), "r"(b0), "r"(b1));
}

// ---------------- kernel 1: im2col (single fp16 plane) ----------------
__global__ void __launch_bounds__(256)
im2col_kernel(const float* __restrict__ x) {
    int idx = blockIdx.x * 256 + threadIdx.x;
    if (idx >= MTOT * 64) return;
    int m = idx >> 6, c64 = idx & 63;
    float v = 0.0f;
    if (c64 < 60) {
        int c = c64 / 15, j = c64 - c * 15;
        int b = m / NOUT, p = m - b * NOUT;
        v = x[b * (4 * LSEQ) + c * LSEQ + p + j];
    }
    g_imh[idx] = __float2half_rn(v);
}

// ---------------- kernel 2 ----------------
__device__ __forceinline__ void stage_w(char* sm, const float* w,
                                        int Ktrue, int Ntrue, int Npad, int KW,
                                        int wo, int tid) {
    __half* wh = reinterpret_cast<__half*>(sm + SM_WHI) + wo;
    __half* wl = reinterpret_cast<__half*>(sm + SM_WLO) + wo;
    int n = Npad * KW;
    for (int i = tid; i < n; i += NTH) {
        int nn = i / KW, kk = i - nn * KW;
        float v = (nn < Ntrue && kk < Ktrue) ? w[kk * Ntrue + nn] : 0.0f;
        __half h = __float2half_rn(v);
        wh[i] = h;
        wl[i] = __float2half_rn(v - __half2float(h));
    }
}

// One layer over TWO M=16 tiles sharing the B stream.
// NTC = compute n-tiles (one full-pad tile skipped; its A frags zero-filled).
template<int KS, int NT, int NTC, int KW, bool LAST>
__device__ __forceinline__ void do_layer2(
        const uint32_t a0[][4], const uint32_t a1[][4],
        uint32_t an0[][4], uint32_t an1[][4],
        uint32_t whb, uint32_t wlb,
        const float* __restrict__ bias, const float* __restrict__ hw,
        int lane, float& p0, float& p1, float& p2, float& p3) {
    const uint32_t brow4 = (uint32_t)(lane & 7) * (KW * 2) + (uint32_t)(lane >> 3) * 16;
    const int col = 2 * (lane & 3);

    #pragma unroll
    for (int n = 0; n < NTC; ++n) {
        float c0 = 0.f, c1 = 0.f, c2 = 0.f, c3 = 0.f;   // tile0 chain
        float d0 = 0.f, d1 = 0.f, d2 = 0.f, d3 = 0.f;   // tile1 chain
        const uint32_t bh = whb + (uint32_t)(n * 8) * (KW * 2) + brow4;
        const uint32_t bl = wlb + (uint32_t)(n * 8) * (KW * 2) + brow4;

        // pass 1: A * Bh
        #pragma unroll
        for (int p = 0; p < KS / 2; ++p) {
            uint32_t b[4];
            ldm_x4(b, bh + p * 64);
            mma16816(c0, c1, c2, c3, a0[2*p],     b[0], b[1]);
            mma16816(d0, d1, d2, d3, a1[2*p],     b[0], b[1]);
            mma16816(c0, c1, c2, c3, a0[2*p + 1], b[2], b[3]);
            mma16816(d0, d1, d2, d3, a1[2*p + 1], b[2], b[3]);
        }
        if (KS & 1) {
            uint32_t b0, b1;
            ldm_x2(b0, b1, bh + (KS - 1) * 32);
            mma16816(c0, c1, c2, c3, a0[KS - 1], b0, b1);
            mma16816(d0, d1, d2, d3, a1[KS - 1], b0, b1);
        }
        // pass 2: A * Bl
        #pragma unroll
        for (int p = 0; p < KS / 2; ++p) {
            uint32_t b[4];
            ldm_x4(b, bl + p * 64);
            mma16816(c0, c1, c2, c3, a0[2*p],     b[0], b[1]);
            mma16816(d0, d1, d2, d3, a1[2*p],     b[0], b[1]);
            mma16816(c0, c1, c2, c3, a0[2*p + 1], b[2], b[3]);
            mma16816(d0, d1, d2, d3, a1[2*p + 1], b[2], b[3]);
        }
        if (KS & 1) {
            uint32_t b0, b1;
            ldm_x2(b0, b1, bl + (KS - 1) * 32);
            mma16816(c0, c1, c2, c3, a0[KS - 1], b0, b1);
            mma16816(d0, d1, d2, d3, a1[KS - 1], b0, b1);
        }

        const int cg = n * 8 + col;
        const float bb0 = bias[cg], bb1 = bias[cg + 1];
        const float g0 = gelu1(c0 + bb0), g1 = gelu1(c1 + bb1);
        const float g2 = gelu1(c2 + bb0), g3 = gelu1(c3 + bb1);
        const float g4 = gelu1(d0 + bb0), g5 = gelu1(d1 + bb1);
        const float g6 = gelu1(d2 + bb0), g7 = gelu1(d3 + bb1);

        if (!LAST) {
            an0[n / 2][(n & 1) * 2 + 0] = pack_f16(g0, g1);
            an0[n / 2][(n & 1) * 2 + 1] = pack_f16(g2, g3);
            an1[n / 2][(n & 1) * 2 + 0] = pack_f16(g4, g5);
            an1[n / 2][(n & 1) * 2 + 1] = pack_f16(g6, g7);
        } else {
            const float w0v = hw[cg], w1v = hw[cg + 1];
            p0 = fmaf(g0, w0v, fmaf(g1, w1v, p0));
            p1 = fmaf(g2, w0v, fmaf(g3, w1v, p1));
            p2 = fmaf(g4, w0v, fmaf(g5, w1v, p2));
            p3 = fmaf(g6, w0v, fmaf(g7, w1v, p3));
        }
    }
    if (!LAST && NTC < NT) {   // skipped full-pad tile: zero its A frags
        an0[NTC / 2][(NTC & 1) * 2 + 0] = 0u;
        an0[NTC / 2][(NTC & 1) * 2 + 1] = 0u;
        an1[NTC / 2][(NTC & 1) * 2 + 0] = 0u;
        an1[NTC / 2][(NTC & 1) * 2 + 1] = 0u;
    }
}

__global__ void __launch_bounds__(NTH, 1)
expert_kernel(const float* __restrict__ w0, const float* __restrict__ b0,
              const float* __restrict__ w1, const float* __restrict__ b1,
              const float* __restrict__ w2, const float* __restrict__ b2,
              const float* __restrict__ w3, const float* __restrict__ b3,
              const float* __restrict__ w4, const float* __restrict__ b4,
              const float* __restrict__ head_w, const float* __restrict__ head_b,
              float* __restrict__ out) {
    extern __shared__ char sm[];
    const uint32_t sb = smem_u32(sm);
    const int k = blockIdx.x;
    const int grp = blockIdx.y;
    const int tid = threadIdx.x;
    const int lane = tid & 31;
    const int wid = tid >> 5;

    {
        float* bm = reinterpret_cast<float*>(sm + SM_BIAS);
        const float* bs[5] = {b0, b1, b2, b3, b4};
        const int ntrue[5] = {72, 86, 86, 71, 59};
        const int npad[5] = {80, 96, 96, 80, 64};
        const int boff[5] = {0, 80, 176, 272, 352};
        #pragma unroll
        for (int L = 0; L < 5; ++L) {
            const float* src = bs[L] + k * ntrue[L];
            for (int i = tid; i < npad[L]; i += NTH)
                bm[boff[L] + i] = (i < ntrue[L]) ? src[i] : 0.0f;
        }
        float* hwm = reinterpret_cast<float*>(sm + SM_HW);
        for (int i = tid; i < 64; i += NTH)
            hwm[i] = (i < 59) ? head_w[i] : 0.0f;
    }
    stage_w(sm, w0 + k * 60 * 72, 60, 72, 80,  72, WO0, tid);
    stage_w(sm, w1 + k * 72 * 86, 72, 86, 96,  88, WO1, tid);
    stage_w(sm, w2 + k * 86 * 86, 86, 86, 96, 104, WO2, tid);
    stage_w(sm, w3 + k * 86 * 71, 86, 71, 80, 104, WO3, tid);
    stage_w(sm, w4 + k * 71 * 59, 71, 59, 64,  88, WO4, tid);
    __syncthreads();

    const float hb = head_b[0];
    const float* bm = reinterpret_cast<const float*>(sm + SM_BIAS);
    const float* hwm = reinterpret_cast<const float*>(sm + SM_HW);
    const int g = lane >> 2;
    const int col0 = 2 * (lane & 3);

    uint32_t A0a[6][4], A0b[6][4], A1a[6][4], A1b[6][4];

    for (int tt = wid; tt < TPP; tt += NWARP) {
        const int pp = grp * TPP + tt;
        if (pp >= NPAIR) continue;
        const int m0 = pp * 32;          // tile0: rows m0..+15, tile1: m0+16..+31

        // layer-0 A fragments from precomputed im2col (both tiles)
        #pragma unroll
        for (int t2 = 0; t2 < 2; ++t2) {
            const char* h0p = (const char*)(g_imh + (m0 + 16 * t2 + g) * 64 + col0);
            const char* h8p = (const char*)(g_imh + (m0 + 16 * t2 + g + 8) * 64 + col0);
            uint32_t (*A)[4] = t2 ? A0b : A0a;
            #pragma unroll
            for (int j = 0; j < 4; ++j) {
                A[j][0] = *(const uint32_t*)(h0p + j * 32);
                A[j][1] = *(const uint32_t*)(h8p + j * 32);
                A[j][2] = *(const uint32_t*)(h0p + j * 32 + 16);
                A[j][3] = *(const uint32_t*)(h8p + j * 32 + 16);
            }
        }

        float p0 = 0.f, p1 = 0.f, p2 = 0.f, p3 = 0.f;
        do_layer2<4, 10,  9,  72, false>(A0a, A0b, A1a, A1b,
            sb + SM_WHI + WO0 * 2, sb + SM_WLO + WO0 * 2, bm + 0,   hwm, lane, p0, p1, p2, p3);
        do_layer2<5, 12, 11,  88, false>(A1a, A1b, A0a, A0b,
            sb + SM_WHI + WO1 * 2, sb + SM_WLO + WO1 * 2, bm + 80,  hwm, lane, p0, p1, p2, p3);
        do_layer2<6, 12, 11, 104, false>(A0a, A0b, A1a, A1b,
            sb + SM_WHI + WO2 * 2, sb + SM_WLO + WO2 * 2, bm + 176, hwm, lane, p0, p1, p2, p3);
        do_layer2<6, 10,  9, 104, false>(A1a, A1b, A0a, A0b,
            sb + SM_WHI + WO3 * 2, sb + SM_WLO + WO3 * 2, bm + 272, hwm, lane, p0, p1, p2, p3);
        do_layer2<5,  8,  8,  88, true >(A0a, A0b, A1a, A1b,
            sb + SM_WHI + WO4 * 2, sb + SM_WLO + WO4 * 2, bm + 352, hwm, lane, p0, p1, p2, p3);

        // head reduce: lanes {4g..4g+3} hold cols of rows g / g+8 per tile
        p0 += __shfl_xor_sync(0xffffffffu, p0, 1);
        p0 += __shfl_xor_sync(0xffffffffu, p0, 2);
        p1 += __shfl_xor_sync(0xffffffffu, p1, 1);
        p1 += __shfl_xor_sync(0xffffffffu, p1, 2);
        p2 += __shfl_xor_sync(0xffffffffu, p2, 1);
        p2 += __shfl_xor_sync(0xffffffffu, p2, 2);
        p3 += __shfl_xor_sync(0xffffffffu, p3, 1);
        p3 += __shfl_xor_sync(0xffffffffu, p3, 2);
        if ((lane & 3) == 0) {
            int m = m0 + g;
            int b = m / NOUT, p = m - b * NOUT;
            out[(b * NK + k) * NOUT + p] = p0 + hb;
            m = m0 + g + 8;  b = m / NOUT; p = m - b * NOUT;
            out[(b * NK + k) * NOUT + p] = p1 + hb;
            m = m0 + 16 + g; b = m / NOUT; p = m - b * NOUT;
            out[(b * NK + k) * NOUT + p] = p2 + hb;
            m = m0 + 24 + g; b = m / NOUT; p = m - b * NOUT;
            out[(b * NK + k) * NOUT + p] = p3 + hb;
        }
    }
}

extern "C" void kernel_launch(void* const* d_in, const int* in_sizes, int n_in,
                              void* d_out, int out_size) {
    const float* x      = (const float*)d_in[0];
    const float* w0     = (const float*)d_in[1];
    const float* b0     = (const float*)d_in[2];
    const float* w1     = (const float*)d_in[3];
    const float* b1     = (const float*)d_in[4];
    const float* w2     = (const float*)d_in[5];
    const float* b2     = (const float*)d_in[6];
    const float* w3     = (const float*)d_in[7];
    const float* b3     = (const float*)d_in[8];
    const float* w4     = (const float*)d_in[9];
    const float* b4     = (const float*)d_in[10];
    const float* head_w = (const float*)d_in[11];
    const float* head_b = (const float*)d_in[12];
    float* out = (float*)d_out;

    im2col_kernel<<<(MTOT * 64 + 255) / 256, 256>>>(x);

    cudaFuncSetAttribute(expert_kernel,
                         cudaFuncAttributeMaxDynamicSharedMemorySize, SMEM_TOTAL);
    dim3 grid(NK, NGRP);
    expert_kernel<<<grid, NTH, SMEM_TOTAL>>>(
        w0, b0, w1, b1, w2, b2, w3, b3, w4, b4, head_w, head_b, out);
}